// round 6
// baseline (speedup 1.0000x reference)
#include <cuda_runtime.h>
#include <cuda_bf16.h>
#include <stdint.h>

#define S 32
#define T 512
#define F 512
#define STEPS 12
#define NEG 32
#define C 33
#define NTH 256

__device__ __nv_bfloat16 g_predT[(size_t)S * STEPS * T * F]; // (s,i,t,f)
__device__ __nv_bfloat16 g_latB[(size_t)S * T * F];
__device__ int g_rows[S * T * C];
__device__ float g_part[S * T];

#define FMA2(a, b, t) asm("fma.rn.f32x2 %0, %1, %2, %0;" : "+l"(a) : "l"(b), "l"(t))

__device__ __forceinline__ uint32_t bf_lo(uint32_t v) { return __byte_perm(v, 0, 0x1044); }
__device__ __forceinline__ uint32_t bf_hi(uint32_t v) { return __byte_perm(v, 0, 0x3244); }

// ---------------------------------------------------------------------------
// Kernel A: precompute gather rows for all (s,u,c)
// ---------------------------------------------------------------------------
__global__ void rows_kernel(const int* __restrict__ negi) {
    int idx = blockIdx.x * 256 + threadIdx.x;
    if (idx >= S * T * C) return;
    int c = idx % C;
    int su = idx / C;
    int u = su & (T - 1);
    int s = su >> 9;
    int row;
    if (c == 0) row = u;
    else {
        int j = (c - 1) * T + u;
        int tsk = j >> 5;
        int raw = negi[s * (NEG * T) + j];
        row = raw + (raw >= tsk ? 1 : 0);
    }
    g_rows[idx] = row;
}

// ---------------------------------------------------------------------------
// Kernel B: latent fp32 -> bf16
// ---------------------------------------------------------------------------
__global__ void latb_kernel(const float* __restrict__ lat) {
    const float4* in = (const float4*)lat;
    uint2* out = (uint2*)g_latB;
    int n4 = S * T * F / 4;
    for (int i = blockIdx.x * blockDim.x + threadIdx.x; i < n4;
         i += gridDim.x * blockDim.x) {
        float4 v = in[i];
        __nv_bfloat162 a = __floats2bfloat162_rn(v.x, v.y);
        __nv_bfloat162 b = __floats2bfloat162_rn(v.z, v.w);
        uint2 h;
        h.x = *(uint32_t*)&a;
        h.y = *(uint32_t*)&b;
        out[i] = h;
    }
}

// ---------------------------------------------------------------------------
// Kernel C: transpose predictions (s,t,f,i) fp32 -> (s,i,t,f) bf16
// ---------------------------------------------------------------------------
__global__ void transpose_kernel(const float* __restrict__ pred) {
    __shared__ float sm[F * 13];
    int st = blockIdx.x;
    const float4* in = (const float4*)(pred + (size_t)st * (F * STEPS));
    for (int x = threadIdx.x; x < F * STEPS / 4; x += blockDim.x) {
        float4 v = in[x];
        int idx = 4 * x;
#pragma unroll
        for (int e = 0; e < 4; e++) {
            int f = (idx + e) / STEPS;
            int i = (idx + e) - f * STEPS;
            sm[f * 13 + i] = ((const float*)&v)[e];
        }
    }
    __syncthreads();
    int s = st >> 9;
    int t = st & (T - 1);
    for (int p = threadIdx.x; p < STEPS * 128; p += blockDim.x) {
        int i = p >> 7;
        int fp2 = p & 127;
        int f = fp2 * 4;
        __nv_bfloat162 h0 = __floats2bfloat162_rn(sm[f * 13 + i], sm[(f + 1) * 13 + i]);
        __nv_bfloat162 h1 = __floats2bfloat162_rn(sm[(f + 2) * 13 + i], sm[(f + 3) * 13 + i]);
        uint2 h;
        h.x = *(uint32_t*)&h0;
        h.y = *(uint32_t*)&h1;
        ((uint2*)(g_predT + ((size_t)((s * STEPS + i) * T + t)) * F))[fp2] = h;
    }
}

// ---------------------------------------------------------------------------
// Kernel D: main. One block per (s,u). 4 blocks/SM (64 regs, 38.8 KB smem).
// T read directly from L2 (g_latB); P staged in smem; 2 step-passes of 6.
// ---------------------------------------------------------------------------
__global__ void __launch_bounds__(NTH, 4)
main_kernel() {
    __shared__ float Pp[256 * 24];      // P: [k-pair][2i] f32
    __shared__ float part[8 * 400];     // per-kgroup partial logits
    __shared__ float logits[400];
    __shared__ float rowloss[16];

    const int u = blockIdx.x;
    const int s = blockIdx.y;
    const int tid = threadIdx.x;
    const int kg = tid >> 5;
    const int l = tid & 31;
    const int cl = l & 15;
    const int ksub = l >> 4;
    const int c0 = cl + 1;

    // row indices for this lane's classes (registers, no smem)
    const int rbase_g = (s * T + u) * C;
    const int rA = g_rows[rbase_g + c0];
    const int rB = g_rows[rbase_g + c0 + 16];
    const int r0 = g_rows[rbase_g];

    // --- stage predictions into Pp[kpair][2i] f32 ---
    const uint4* pu4 = (const uint4*)g_predT;
    for (int x = tid; x < STEPS * 64; x += NTH) {
        int i = x % STEPS;
        int r = x / STEPS;
        float2 v[4];
        if (i <= u) {
            uint4 raw = pu4[((size_t)((s * STEPS + i) * T + (u - i))) * 64 + r];
            const uint32_t* w = (const uint32_t*)&raw;
#pragma unroll
            for (int j = 0; j < 4; j++) {
                v[j].x = __uint_as_float(bf_lo(w[j]));
                v[j].y = __uint_as_float(bf_hi(w[j]));
            }
        } else {
            v[0] = v[1] = v[2] = v[3] = make_float2(0.f, 0.f);
        }
#pragma unroll
        for (int j = 0; j < 4; j++)
            *(float2*)(Pp + (4 * r + j) * 24 + 2 * i) = v[j];
    }
    __syncthreads();

    // --- GEMM: 2 classes/lane, 16 k-pairs/lane, 2 passes of 6 steps ---
    const uint4* TA = ((const uint4*)g_latB) + ((size_t)(s * T + rA)) * 64 + kg * 8 + ksub * 4;
    const uint4* TB = ((const uint4*)g_latB) + ((size_t)(s * T + rB)) * 64 + kg * 8 + ksub * 4;
    const float* Pbase = Pp + (kg * 32 + ksub * 16) * 24;
    // rotated quarter offsets (floats within the pass's 12-float half-row)
    const int qo0 = ksub ? 4 : 0;
    const int qo1 = ksub ? 8 : 4;
    const int qo2 = ksub ? 0 : 8;

#pragma unroll
    for (int p = 0; p < 2; p++) {
        unsigned long long accA[6], accB[6];
#pragma unroll
        for (int t2 = 0; t2 < 6; t2++) { accA[t2] = 0ULL; accB[t2] = 0ULL; }

        uint4 tqa = TA[0];
        uint4 tqb = TB[0];
#pragma unroll
        for (int m = 0; m < 4; m++) {
            uint4 ca = tqa, cb = tqb;
            if (m < 3) { tqa = TA[m + 1]; tqb = TB[m + 1]; }
#pragma unroll
            for (int kk = 0; kk < 4; kk++) {
                const float* Pr = Pbase + (4 * m + kk) * 24 + 12 * p;
                uint32_t wa = ((const uint32_t*)&ca)[kk];
                uint32_t wb = ((const uint32_t*)&cb)[kk];
                unsigned long long tva, tvb;
                asm("mov.b64 %0, {%1, %2};" : "=l"(tva) : "r"(bf_lo(wa)), "r"(bf_hi(wa)));
                asm("mov.b64 %0, {%1, %2};" : "=l"(tvb) : "r"(bf_lo(wb)), "r"(bf_hi(wb)));
                ulonglong2 q0 = *(const ulonglong2*)(Pr + qo0);
                ulonglong2 q1 = *(const ulonglong2*)(Pr + qo1);
                ulonglong2 q2 = *(const ulonglong2*)(Pr + qo2);
                FMA2(accA[0], q0.x, tva); FMA2(accA[1], q0.y, tva);
                FMA2(accB[0], q0.x, tvb); FMA2(accB[1], q0.y, tvb);
                FMA2(accA[2], q1.x, tva); FMA2(accA[3], q1.y, tva);
                FMA2(accB[2], q1.x, tvb); FMA2(accB[3], q1.y, tvb);
                FMA2(accA[4], q2.x, tva); FMA2(accA[5], q2.y, tva);
                FMA2(accB[4], q2.x, tvb); FMA2(accB[5], q2.y, tvb);
            }
        }
        // pair-sum + de-rotate combine across ksub halves
        float sA[6], sB[6];
#pragma unroll
        for (int t2 = 0; t2 < 6; t2++) {
            float2 va = *(float2*)&accA[t2];
            float2 vb = *(float2*)&accB[t2];
            sA[t2] = va.x + va.y;
            sB[t2] = vb.x + vb.y;
        }
#pragma unroll
        for (int d = 0; d < 3; d++) {
#pragma unroll
            for (int e = 0; e < 2; e++) {
                const int dst = 2 * d + e;
                const int src = 2 * ((d + 2) % 3) + e;
                float vA = sA[dst] + __shfl_xor_sync(0xFFFFFFFFu, sA[src], 16);
                float vB = sB[dst] + __shfl_xor_sync(0xFFFFFFFFu, sB[src], 16);
                if (ksub == 0) {
                    int i = 6 * p + 2 * d + e;
                    part[kg * 400 + i * C + c0] = vA;
                    part[kg * 400 + i * C + c0 + 16] = vB;
                }
            }
        }
    }

    // --- positive class: one k-pair per lane, all 12 steps ---
    {
        uint32_t t0w = ((const uint32_t*)g_latB)[(size_t)(s * T + r0) * 256 + kg * 32 + l];
        unsigned long long tv0;
        asm("mov.b64 %0, {%1, %2};" : "=l"(tv0) : "r"(bf_lo(t0w)), "r"(bf_hi(t0w)));
        unsigned long long ap[STEPS];
#pragma unroll
        for (int i = 0; i < STEPS; i++) ap[i] = 0ULL;
        const ulonglong2* pp = (const ulonglong2*)(Pp + (kg * 32 + l) * 24);
#pragma unroll
        for (int j = 0; j < 6; j++) {
            ulonglong2 pq = pp[j];
            FMA2(ap[2 * j],     pq.x, tv0);
            FMA2(ap[2 * j + 1], pq.y, tv0);
        }
#pragma unroll
        for (int i = 0; i < STEPS; i++) {
            float2 v = *(float2*)&ap[i];
            float p = v.x + v.y;
            p += __shfl_down_sync(0xFFFFFFFFu, p, 16);
            p += __shfl_down_sync(0xFFFFFFFFu, p, 8);
            p += __shfl_down_sync(0xFFFFFFFFu, p, 4);
            p += __shfl_down_sync(0xFFFFFFFFu, p, 2);
            p += __shfl_down_sync(0xFFFFFFFFu, p, 1);
            if (l == 0) part[kg * 400 + i * C] = p;
        }
    }
    __syncthreads();

    // --- reduce over 8 k-groups ---
    for (int o = tid; o < STEPS * C; o += NTH) {
        float ssum = 0.f;
#pragma unroll
        for (int g = 0; g < 8; g++) ssum += part[g * 400 + o];
        logits[o] = ssum;
    }
    __syncthreads();

    // --- warp-parallel logsumexp: warp kg handles steps kg, kg+8 ---
    for (int i = kg; i < STEPS; i += 8) {
        float rl = 0.f;
        if (i <= u) {
            float v = logits[i * C + l];
            float v32 = logits[i * C + 32];
            float m = fmaxf(v, v32);
#pragma unroll
            for (int off = 16; off > 0; off >>= 1)
                m = fmaxf(m, __shfl_xor_sync(0xFFFFFFFFu, m, off));
            float e = __expf(v - m);
#pragma unroll
            for (int off = 16; off > 0; off >>= 1)
                e += __shfl_xor_sync(0xFFFFFFFFu, e, off);
            float total = e + __expf(v32 - m);
            rl = m + __logf(total) - logits[i * C];
        }
        if (l == 0) rowloss[i] = rl;
    }
    __syncthreads();
    if (tid == 0) {
        float bl = 0.f;
#pragma unroll
        for (int i = 0; i < STEPS; i++) bl += rowloss[i];
        g_part[s * T + u] = bl;
    }
}

// ---------------------------------------------------------------------------
// Kernel E: deterministic final reduction
// ---------------------------------------------------------------------------
__global__ void reduce_kernel(float* __restrict__ out) {
    __shared__ float sm[512];
    int tid = threadIdx.x;
    float s0 = 0.f;
    for (int i = tid; i < S * T; i += 512) s0 += g_part[i];
    sm[tid] = s0;
    __syncthreads();
    for (int st = 256; st > 0; st >>= 1) {
        if (tid < st) sm[tid] += sm[tid + st];
        __syncthreads();
    }
    if (tid == 0) out[0] = sm[0];
}

extern "C" void kernel_launch(void* const* d_in, const int* in_sizes, int n_in,
                              void* d_out, int out_size) {
    const float* lat  = (const float*)d_in[0];
    const float* pred = (const float*)d_in[1];
    const int*   negi = (const int*)d_in[2];
    float* out = (float*)d_out;

    rows_kernel<<<(S * T * C + 255) / 256, 256>>>(negi);
    latb_kernel<<<1024, 256>>>(lat);
    transpose_kernel<<<S * T, 256>>>(pred);
    main_kernel<<<dim3(T, S), NTH>>>();
    reduce_kernel<<<1, 512>>>(out);
}

// round 7
// speedup vs baseline: 1.0007x; 1.0007x over previous
#include <cuda_runtime.h>
#include <cuda_bf16.h>
#include <stdint.h>

#define S 32
#define T 512
#define F 512
#define STEPS 12
#define NEG 32
#define C 33
#define NTH 256

__device__ __nv_bfloat16 g_predT[(size_t)S * STEPS * T * F]; // (s,i,t,f)
__device__ __nv_bfloat16 g_latB[(size_t)S * T * F];
__device__ int g_rows[S * T * C];
__device__ float g_part[S * T];

#define FMA2(a, b, t) asm("fma.rn.f32x2 %0, %1, %2, %0;" : "+l"(a) : "l"(b), "l"(t))

__device__ __forceinline__ uint32_t bf_lo(uint32_t v) { return __byte_perm(v, 0, 0x1044); }
__device__ __forceinline__ uint32_t bf_hi(uint32_t v) { return __byte_perm(v, 0, 0x3244); }

// ---------------------------------------------------------------------------
// Kernel A: precompute gather rows for all (s,u,c)
// ---------------------------------------------------------------------------
__global__ void rows_kernel(const int* __restrict__ negi) {
    int idx = blockIdx.x * 256 + threadIdx.x;
    if (idx >= S * T * C) return;
    int c = idx % C;
    int su = idx / C;
    int u = su & (T - 1);
    int s = su >> 9;
    int row;
    if (c == 0) row = u;
    else {
        int j = (c - 1) * T + u;
        int tsk = j >> 5;
        int raw = negi[s * (NEG * T) + j];
        row = raw + (raw >= tsk ? 1 : 0);
    }
    g_rows[idx] = row;
}

// ---------------------------------------------------------------------------
// Kernel B: latent fp32 -> bf16
// ---------------------------------------------------------------------------
__global__ void latb_kernel(const float* __restrict__ lat) {
    const float4* in = (const float4*)lat;
    uint2* out = (uint2*)g_latB;
    int n4 = S * T * F / 4;
    for (int i = blockIdx.x * blockDim.x + threadIdx.x; i < n4;
         i += gridDim.x * blockDim.x) {
        float4 v = in[i];
        __nv_bfloat162 a = __floats2bfloat162_rn(v.x, v.y);
        __nv_bfloat162 b = __floats2bfloat162_rn(v.z, v.w);
        uint2 h;
        h.x = *(uint32_t*)&a;
        h.y = *(uint32_t*)&b;
        out[i] = h;
    }
}

// ---------------------------------------------------------------------------
// Kernel C: transpose predictions (s,t,f,i) fp32 -> (s,i,t,f) bf16
// ---------------------------------------------------------------------------
__global__ void transpose_kernel(const float* __restrict__ pred) {
    __shared__ float sm[F * 13];
    int st = blockIdx.x;
    const float4* in = (const float4*)(pred + (size_t)st * (F * STEPS));
    for (int x = threadIdx.x; x < F * STEPS / 4; x += blockDim.x) {
        float4 v = in[x];
        int idx = 4 * x;
#pragma unroll
        for (int e = 0; e < 4; e++) {
            int f = (idx + e) / STEPS;
            int i = (idx + e) - f * STEPS;
            sm[f * 13 + i] = ((const float*)&v)[e];
        }
    }
    __syncthreads();
    int s = st >> 9;
    int t = st & (T - 1);
    for (int p = threadIdx.x; p < STEPS * 128; p += blockDim.x) {
        int i = p >> 7;
        int fp2 = p & 127;
        int f = fp2 * 4;
        __nv_bfloat162 h0 = __floats2bfloat162_rn(sm[f * 13 + i], sm[(f + 1) * 13 + i]);
        __nv_bfloat162 h1 = __floats2bfloat162_rn(sm[(f + 2) * 13 + i], sm[(f + 3) * 13 + i]);
        uint2 h;
        h.x = *(uint32_t*)&h0;
        h.y = *(uint32_t*)&h1;
        ((uint2*)(g_predT + ((size_t)((s * STEPS + i) * T + t)) * F))[fp2] = h;
    }
}

// ---------------------------------------------------------------------------
// Kernel D: main. One block per (s,u). 4 blocks/SM (64 regs, 38.8 KB smem).
// T read directly from L2 (g_latB); P staged in smem; 2 step-passes of 6.
// ---------------------------------------------------------------------------
__global__ void __launch_bounds__(NTH, 4)
main_kernel() {
    __shared__ float Pp[256 * 24];      // P: [k-pair][2i] f32
    __shared__ float part[8 * 400];     // per-kgroup partial logits
    __shared__ float logits[400];
    __shared__ float rowloss[16];

    const int u = blockIdx.x;
    const int s = blockIdx.y;
    const int tid = threadIdx.x;
    const int kg = tid >> 5;
    const int l = tid & 31;
    const int cl = l & 15;
    const int ksub = l >> 4;
    const int c0 = cl + 1;

    // row indices for this lane's classes (registers, no smem)
    const int rbase_g = (s * T + u) * C;
    const int rA = g_rows[rbase_g + c0];
    const int rB = g_rows[rbase_g + c0 + 16];
    const int r0 = g_rows[rbase_g];

    // --- stage predictions into Pp[kpair][2i] f32 ---
    const uint4* pu4 = (const uint4*)g_predT;
    for (int x = tid; x < STEPS * 64; x += NTH) {
        int i = x % STEPS;
        int r = x / STEPS;
        float2 v[4];
        if (i <= u) {
            uint4 raw = pu4[((size_t)((s * STEPS + i) * T + (u - i))) * 64 + r];
            const uint32_t* w = (const uint32_t*)&raw;
#pragma unroll
            for (int j = 0; j < 4; j++) {
                v[j].x = __uint_as_float(bf_lo(w[j]));
                v[j].y = __uint_as_float(bf_hi(w[j]));
            }
        } else {
            v[0] = v[1] = v[2] = v[3] = make_float2(0.f, 0.f);
        }
#pragma unroll
        for (int j = 0; j < 4; j++)
            *(float2*)(Pp + (4 * r + j) * 24 + 2 * i) = v[j];
    }
    __syncthreads();

    // --- GEMM: 2 classes/lane, 16 k-pairs/lane, 2 passes of 6 steps ---
    const uint4* TA = ((const uint4*)g_latB) + ((size_t)(s * T + rA)) * 64 + kg * 8 + ksub * 4;
    const uint4* TB = ((const uint4*)g_latB) + ((size_t)(s * T + rB)) * 64 + kg * 8 + ksub * 4;
    const float* Pbase = Pp + (kg * 32 + ksub * 16) * 24;
    // rotated quarter offsets (floats within the pass's 12-float half-row)
    const int qo0 = ksub ? 4 : 0;
    const int qo1 = ksub ? 8 : 4;
    const int qo2 = ksub ? 0 : 8;

#pragma unroll
    for (int p = 0; p < 2; p++) {
        unsigned long long accA[6], accB[6];
#pragma unroll
        for (int t2 = 0; t2 < 6; t2++) { accA[t2] = 0ULL; accB[t2] = 0ULL; }

        uint4 tqa = TA[0];
        uint4 tqb = TB[0];
#pragma unroll
        for (int m = 0; m < 4; m++) {
            uint4 ca = tqa, cb = tqb;
            if (m < 3) { tqa = TA[m + 1]; tqb = TB[m + 1]; }
#pragma unroll
            for (int kk = 0; kk < 4; kk++) {
                const float* Pr = Pbase + (4 * m + kk) * 24 + 12 * p;
                uint32_t wa = ((const uint32_t*)&ca)[kk];
                uint32_t wb = ((const uint32_t*)&cb)[kk];
                unsigned long long tva, tvb;
                asm("mov.b64 %0, {%1, %2};" : "=l"(tva) : "r"(bf_lo(wa)), "r"(bf_hi(wa)));
                asm("mov.b64 %0, {%1, %2};" : "=l"(tvb) : "r"(bf_lo(wb)), "r"(bf_hi(wb)));
                ulonglong2 q0 = *(const ulonglong2*)(Pr + qo0);
                ulonglong2 q1 = *(const ulonglong2*)(Pr + qo1);
                ulonglong2 q2 = *(const ulonglong2*)(Pr + qo2);
                FMA2(accA[0], q0.x, tva); FMA2(accA[1], q0.y, tva);
                FMA2(accB[0], q0.x, tvb); FMA2(accB[1], q0.y, tvb);
                FMA2(accA[2], q1.x, tva); FMA2(accA[3], q1.y, tva);
                FMA2(accB[2], q1.x, tvb); FMA2(accB[3], q1.y, tvb);
                FMA2(accA[4], q2.x, tva); FMA2(accA[5], q2.y, tva);
                FMA2(accB[4], q2.x, tvb); FMA2(accB[5], q2.y, tvb);
            }
        }
        // pair-sum + de-rotate combine across ksub halves
        float sA[6], sB[6];
#pragma unroll
        for (int t2 = 0; t2 < 6; t2++) {
            float2 va = *(float2*)&accA[t2];
            float2 vb = *(float2*)&accB[t2];
            sA[t2] = va.x + va.y;
            sB[t2] = vb.x + vb.y;
        }
#pragma unroll
        for (int d = 0; d < 3; d++) {
#pragma unroll
            for (int e = 0; e < 2; e++) {
                const int dst = 2 * d + e;
                const int src = 2 * ((d + 2) % 3) + e;
                float vA = sA[dst] + __shfl_xor_sync(0xFFFFFFFFu, sA[src], 16);
                float vB = sB[dst] + __shfl_xor_sync(0xFFFFFFFFu, sB[src], 16);
                if (ksub == 0) {
                    int i = 6 * p + 2 * d + e;
                    part[kg * 400 + i * C + c0] = vA;
                    part[kg * 400 + i * C + c0 + 16] = vB;
                }
            }
        }
    }

    // --- positive class: one k-pair per lane, all 12 steps ---
    {
        uint32_t t0w = ((const uint32_t*)g_latB)[(size_t)(s * T + r0) * 256 + kg * 32 + l];
        unsigned long long tv0;
        asm("mov.b64 %0, {%1, %2};" : "=l"(tv0) : "r"(bf_lo(t0w)), "r"(bf_hi(t0w)));
        unsigned long long ap[STEPS];
#pragma unroll
        for (int i = 0; i < STEPS; i++) ap[i] = 0ULL;
        const ulonglong2* pp = (const ulonglong2*)(Pp + (kg * 32 + l) * 24);
#pragma unroll
        for (int j = 0; j < 6; j++) {
            ulonglong2 pq = pp[j];
            FMA2(ap[2 * j],     pq.x, tv0);
            FMA2(ap[2 * j + 1], pq.y, tv0);
        }
#pragma unroll
        for (int i = 0; i < STEPS; i++) {
            float2 v = *(float2*)&ap[i];
            float p = v.x + v.y;
            p += __shfl_down_sync(0xFFFFFFFFu, p, 16);
            p += __shfl_down_sync(0xFFFFFFFFu, p, 8);
            p += __shfl_down_sync(0xFFFFFFFFu, p, 4);
            p += __shfl_down_sync(0xFFFFFFFFu, p, 2);
            p += __shfl_down_sync(0xFFFFFFFFu, p, 1);
            if (l == 0) part[kg * 400 + i * C] = p;
        }
    }
    __syncthreads();

    // --- reduce over 8 k-groups ---
    for (int o = tid; o < STEPS * C; o += NTH) {
        float ssum = 0.f;
#pragma unroll
        for (int g = 0; g < 8; g++) ssum += part[g * 400 + o];
        logits[o] = ssum;
    }
    __syncthreads();

    // --- warp-parallel logsumexp: warp kg handles steps kg, kg+8 ---
    for (int i = kg; i < STEPS; i += 8) {
        float rl = 0.f;
        if (i <= u) {
            float v = logits[i * C + l];
            float v32 = logits[i * C + 32];
            float m = fmaxf(v, v32);
#pragma unroll
            for (int off = 16; off > 0; off >>= 1)
                m = fmaxf(m, __shfl_xor_sync(0xFFFFFFFFu, m, off));
            float e = __expf(v - m);
#pragma unroll
            for (int off = 16; off > 0; off >>= 1)
                e += __shfl_xor_sync(0xFFFFFFFFu, e, off);
            float total = e + __expf(v32 - m);
            rl = m + __logf(total) - logits[i * C];
        }
        if (l == 0) rowloss[i] = rl;
    }
    __syncthreads();
    if (tid == 0) {
        float bl = 0.f;
#pragma unroll
        for (int i = 0; i < STEPS; i++) bl += rowloss[i];
        g_part[s * T + u] = bl;
    }
}

// ---------------------------------------------------------------------------
// Kernel E: deterministic final reduction
// ---------------------------------------------------------------------------
__global__ void reduce_kernel(float* __restrict__ out) {
    __shared__ float sm[512];
    int tid = threadIdx.x;
    float s0 = 0.f;
    for (int i = tid; i < S * T; i += 512) s0 += g_part[i];
    sm[tid] = s0;
    __syncthreads();
    for (int st = 256; st > 0; st >>= 1) {
        if (tid < st) sm[tid] += sm[tid + st];
        __syncthreads();
    }
    if (tid == 0) out[0] = sm[0];
}

extern "C" void kernel_launch(void* const* d_in, const int* in_sizes, int n_in,
                              void* d_out, int out_size) {
    const float* lat  = (const float*)d_in[0];
    const float* pred = (const float*)d_in[1];
    const int*   negi = (const int*)d_in[2];
    float* out = (float*)d_out;

    rows_kernel<<<(S * T * C + 255) / 256, 256>>>(negi);
    latb_kernel<<<1024, 256>>>(lat);
    transpose_kernel<<<S * T, 256>>>(pred);
    main_kernel<<<dim3(T, S), NTH>>>();
    reduce_kernel<<<1, 512>>>(out);
}

// round 8
// speedup vs baseline: 1.6423x; 1.6411x over previous
#include <cuda_runtime.h>
#include <cuda_bf16.h>
#include <stdint.h>

#define S 32
#define T 512
#define F 512
#define STEPS 12
#define NEG 32
#define C 33
#define NTH 256

// smem layout in 4-byte words
#define T_OFF    0                      // T: 33 x 256 u32 (bf16x2), XOR-swizzled
#define PP_OFF   8448                   // P: 256 rows x 24 f32
#define PART_OFF (PP_OFF + 6144)        // 14592: 8 kg x 400
#define LG_OFF   (PART_OFF + 3200)      // 17792: 396 (+4)
#define RS_OFF   (LG_OFF + 400)         // 18192: 33 (+3)
#define RL_OFF   (RS_OFF + 36)          // 18228: 12 (+4)
#define POS_OFF  (RL_OFF + 16)          // 18244: 768 positive partials
#define SMEM_WORDS (POS_OFF + 768)      // 19012 words = 76048 B (x3 = 228.1 KB/SM)

__device__ __nv_bfloat16 g_predT[(size_t)S * STEPS * T * F]; // (s,i,t,f)
__device__ __nv_bfloat16 g_latB[(size_t)S * T * F];
__device__ float g_part[S * T];

#define FMA2(a, b, t) asm("fma.rn.f32x2 %0, %1, %2, %0;" : "+l"(a) : "l"(b), "l"(t))

__device__ __forceinline__ uint32_t bf_lo(uint32_t v) { return __byte_perm(v, 0, 0x1044); }
__device__ __forceinline__ uint32_t bf_hi(uint32_t v) { return __byte_perm(v, 0, 0x3244); }

__global__ void init_kernel() {
    if (blockIdx.x == 0 && threadIdx.x == 0) g_part[0] = 0.f;
}

// ---------------------------------------------------------------------------
// Kernel 1: latent fp32 -> bf16
// ---------------------------------------------------------------------------
__global__ void latb_kernel(const float* __restrict__ lat) {
    const float4* in = (const float4*)lat;
    uint2* out = (uint2*)g_latB;
    int n4 = S * T * F / 4;
    for (int i = blockIdx.x * blockDim.x + threadIdx.x; i < n4;
         i += gridDim.x * blockDim.x) {
        float4 v = in[i];
        __nv_bfloat162 a = __floats2bfloat162_rn(v.x, v.y);
        __nv_bfloat162 b = __floats2bfloat162_rn(v.z, v.w);
        uint2 h;
        h.x = *(uint32_t*)&a;
        h.y = *(uint32_t*)&b;
        out[i] = h;
    }
}

// ---------------------------------------------------------------------------
// Kernel 2: transpose predictions (s,t,f,i) fp32 -> (s,i,t,f) bf16
// ---------------------------------------------------------------------------
__global__ void transpose_kernel(const float* __restrict__ pred) {
    __shared__ float sm[F * 13];
    int st = blockIdx.x;
    const float4* in = (const float4*)(pred + (size_t)st * (F * STEPS));
    for (int x = threadIdx.x; x < F * STEPS / 4; x += blockDim.x) {
        float4 v = in[x];
        int idx = 4 * x;
#pragma unroll
        for (int e = 0; e < 4; e++) {
            int f = (idx + e) / STEPS;
            int i = (idx + e) - f * STEPS;
            sm[f * 13 + i] = ((const float*)&v)[e];
        }
    }
    __syncthreads();
    int s = st >> 9;
    int t = st & (T - 1);
    for (int p = threadIdx.x; p < STEPS * 128; p += blockDim.x) {
        int i = p >> 7;
        int fp2 = p & 127;
        int f = fp2 * 4;
        __nv_bfloat162 h0 = __floats2bfloat162_rn(sm[f * 13 + i], sm[(f + 1) * 13 + i]);
        __nv_bfloat162 h1 = __floats2bfloat162_rn(sm[(f + 2) * 13 + i], sm[(f + 3) * 13 + i]);
        uint2 h;
        h.x = *(uint32_t*)&h0;
        h.y = *(uint32_t*)&h1;
        ((uint2*)(g_predT + ((size_t)((s * STEPS + i) * T + t)) * F))[fp2] = h;
    }
}

// ---------------------------------------------------------------------------
// Kernel 3: main. One block per (s,u). Warp = k-group, lane = (class, ksub).
// Positive class computed during staging (posp partials), not in GEMM.
// ---------------------------------------------------------------------------
__global__ void __launch_bounds__(NTH, 3)
main_kernel(const int* __restrict__ negi) {
    extern __shared__ uint32_t smw[];
    uint32_t* Tw     = smw + T_OFF;
    float*    Pp     = (float*)(smw + PP_OFF);
    float*    part   = (float*)(smw + PART_OFF);
    float*    logits = (float*)(smw + LG_OFF);
    int*      rowsm  = (int*)(smw + RS_OFF);
    float*    rowloss= (float*)(smw + RL_OFF);
    float*    posp   = (float*)(smw + POS_OFF);

    const int u = blockIdx.x;
    const int s = blockIdx.y;
    const int tid = threadIdx.x;

    if (tid < C) {
        int row;
        if (tid == 0) row = u;
        else {
            int j = (tid - 1) * T + u;
            int tsk = j >> 5;
            int raw = negi[s * (NEG * T) + j];
            row = raw + (raw >= tsk ? 1 : 0);
        }
        rowsm[tid] = row;
    }
    __syncthreads();

    // --- stage targets: bf16 copy, XOR-swizzled 16B granules, STS.128 ---
    const uint4* latu4 = (const uint4*)g_latB;
    for (int x = tid; x < C * 64; x += NTH) {
        int c = x >> 6;
        int q = x & 63;
        uint4 raw = latu4[((size_t)(s * T + rowsm[c])) * 64 + q];
        *(uint4*)(Tw + c * 256 + ((q ^ (c & 7)) << 2)) = raw;
    }

    // --- stage predictions into Pp[kpair][2i]; fuse positive-class partials ---
    const uint4* pu4 = (const uint4*)g_predT;
    for (int x = tid; x < STEPS * 64; x += NTH) {
        int i = x % STEPS;
        int r = x / STEPS;                 // uint4 granule = 4 k-pairs
        float2 v[4];
        unsigned long long pacc = 0ULL;
        if (i <= u) {
            uint4 raw = pu4[((size_t)((s * STEPS + i) * T + (u - i))) * 64 + r];
            const uint32_t* w = (const uint32_t*)&raw;
#pragma unroll
            for (int j = 0; j < 4; j++) {
                v[j].x = __uint_as_float(bf_lo(w[j]));
                v[j].y = __uint_as_float(bf_hi(w[j]));
            }
            // positive class: target row u, same granule
            uint4 t4 = latu4[((size_t)(s * T + u)) * 64 + r];
            const uint32_t* tw = (const uint32_t*)&t4;
#pragma unroll
            for (int j = 0; j < 4; j++) {
                unsigned long long tv, pv;
                asm("mov.b64 %0, {%1, %2};" : "=l"(tv) : "r"(bf_lo(tw[j])), "r"(bf_hi(tw[j])));
                asm("mov.b64 %0, {%1, %2};" : "=l"(pv) : "f"(v[j].x), "f"(v[j].y));
                FMA2(pacc, pv, tv);
            }
        } else {
            v[0] = v[1] = v[2] = v[3] = make_float2(0.f, 0.f);
        }
#pragma unroll
        for (int j = 0; j < 4; j++)
            *(float2*)(Pp + (4 * r + j) * 24 + 2 * i) = v[j];
        float2 pw = *(float2*)&pacc;
        posp[x] = pw.x + pw.y;
    }
    __syncthreads();

    // --- GEMM: 2 negative classes/lane, 16 k-pairs/lane, 12 steps ---
    const int kg   = tid >> 5;
    const int l    = tid & 31;
    const int cl   = l & 15;
    const int ksub = l >> 4;
    const int c0   = cl + 1;
    const int sw   = c0 & 7;
    const int gbase = kg * 8 + ksub * 4;
    const int rbase = kg * 32 + ksub * 16;
    const int koff  = 12 * ksub;

    unsigned long long a0[STEPS], a1[STEPS];
#pragma unroll
    for (int i = 0; i < STEPS; i++) { a0[i] = 0ULL; a1[i] = 0ULL; }

#pragma unroll
    for (int m = 0; m < 4; m++) {
        int tix = ((gbase + m) ^ sw) << 2;
        uint4 tq0 = *(const uint4*)(Tw + c0 * 256 + tix);
        uint4 tq1 = *(const uint4*)(Tw + (c0 + 16) * 256 + tix);
#pragma unroll
        for (int kk = 0; kk < 4; kk++) {
            int r = rbase + 4 * m + kk;
            const float* pA = Pp + r * 24 + koff;
            const float* pB = pA - 2 * koff;
            uint32_t w0 = ((const uint32_t*)&tq0)[kk];
            uint32_t w1 = ((const uint32_t*)&tq1)[kk];
            unsigned long long tv0, tv1;
            asm("mov.b64 %0, {%1, %2};" : "=l"(tv0) : "r"(bf_lo(w0)), "r"(bf_hi(w0)));
            asm("mov.b64 %0, {%1, %2};" : "=l"(tv1) : "r"(bf_lo(w1)), "r"(bf_hi(w1)));
#pragma unroll
            for (int q = 0; q < 3; q++) {
                ulonglong2 pq = *(const ulonglong2*)(pA + 4 * q);
                FMA2(a0[2 * q],     pq.x, tv0);
                FMA2(a0[2 * q + 1], pq.y, tv0);
                FMA2(a1[2 * q],     pq.x, tv1);
                FMA2(a1[2 * q + 1], pq.y, tv1);
            }
#pragma unroll
            for (int q = 3; q < 6; q++) {
                ulonglong2 pq = *(const ulonglong2*)(pB + 4 * q);
                FMA2(a0[2 * q],     pq.x, tv0);
                FMA2(a0[2 * q + 1], pq.y, tv0);
                FMA2(a1[2 * q],     pq.x, tv1);
                FMA2(a1[2 * q + 1], pq.y, tv1);
            }
        }
    }

    float s0[STEPS], s1[STEPS];
#pragma unroll
    for (int i = 0; i < STEPS; i++) {
        float2 v0 = *(float2*)&a0[i];
        float2 v1 = *(float2*)&a1[i];
        s0[i] = v0.x + v0.y;
        s1[i] = v1.x + v1.y;
    }
#pragma unroll
    for (int q = 0; q < 6; q++) {
        const int qp = (q + 3) % 6;
        float vA0 = s0[2 * q]     + __shfl_xor_sync(0xFFFFFFFFu, s0[2 * qp], 16);
        float vA1 = s0[2 * q + 1] + __shfl_xor_sync(0xFFFFFFFFu, s0[2 * qp + 1], 16);
        float vB0 = s1[2 * q]     + __shfl_xor_sync(0xFFFFFFFFu, s1[2 * qp], 16);
        float vB1 = s1[2 * q + 1] + __shfl_xor_sync(0xFFFFFFFFu, s1[2 * qp + 1], 16);
        if (ksub == 0) {
            part[kg * 400 + (2 * q) * C + c0]          = vA0;
            part[kg * 400 + (2 * q + 1) * C + c0]      = vA1;
            part[kg * 400 + (2 * q) * C + c0 + 16]     = vB0;
            part[kg * 400 + (2 * q + 1) * C + c0 + 16] = vB1;
        }
    }
    __syncthreads();

    // --- assemble logits: class 0 from posp, classes 1..32 from part ---
    for (int o = tid; o < STEPS * C; o += NTH) {
        int i = o / C;
        int c2 = o - i * C;
        float ssum = 0.f;
        if (c2 == 0) {
            for (int rr = 0; rr < 64; rr++) ssum += posp[rr * STEPS + i];
        } else {
#pragma unroll
            for (int g = 0; g < 8; g++) ssum += part[g * 400 + o];
        }
        logits[o] = ssum;
    }
    __syncthreads();

    // --- warp-parallel logsumexp: warp kg handles steps kg, kg+8 ---
    for (int i = kg; i < STEPS; i += 8) {
        float rl = 0.f;
        if (i <= u) {
            float v = logits[i * C + l];
            float v32 = logits[i * C + 32];
            float m = fmaxf(v, v32);
#pragma unroll
            for (int off = 16; off > 0; off >>= 1)
                m = fmaxf(m, __shfl_xor_sync(0xFFFFFFFFu, m, off));
            float e = __expf(v - m);
#pragma unroll
            for (int off = 16; off > 0; off >>= 1)
                e += __shfl_xor_sync(0xFFFFFFFFu, e, off);
            float total = e + __expf(v32 - m);
            rl = m + __logf(total) - logits[i * C];
        }
        if (l == 0) rowloss[i] = rl;
    }
    __syncthreads();
    if (tid == 0) {
        float bl = 0.f;
#pragma unroll
        for (int i = 0; i < STEPS; i++) bl += rowloss[i];
        g_part[s * T + u] = bl;
    }
}

// ---------------------------------------------------------------------------
// Kernel 4: deterministic final reduction
// ---------------------------------------------------------------------------
__global__ void reduce_kernel(float* __restrict__ out) {
    __shared__ float sm[512];
    int tid = threadIdx.x;
    float s0 = 0.f;
    for (int i = tid; i < S * T; i += 512) s0 += g_part[i];
    sm[tid] = s0;
    __syncthreads();
    for (int st = 256; st > 0; st >>= 1) {
        if (tid < st) sm[tid] += sm[tid + st];
        __syncthreads();
    }
    if (tid == 0) out[0] = sm[0];
}

extern "C" void kernel_launch(void* const* d_in, const int* in_sizes, int n_in,
                              void* d_out, int out_size) {
    const float* lat  = (const float*)d_in[0];
    const float* pred = (const float*)d_in[1];
    const int*   negi = (const int*)d_in[2];
    float* out = (float*)d_out;

    cudaFuncSetAttribute(main_kernel, cudaFuncAttributeMaxDynamicSharedMemorySize,
                         SMEM_WORDS * 4);

    init_kernel<<<1, 32>>>();
    latb_kernel<<<1024, 256>>>(lat);
    transpose_kernel<<<S * T, 256>>>(pred);
    main_kernel<<<dim3(T, S), NTH, SMEM_WORDS * 4>>>(negi);
    reduce_kernel<<<1, 512>>>(out);
}